// round 1
// baseline (speedup 1.0000x reference)
#include <cuda_runtime.h>

#define P_  8
#define B_  8
#define C_  128
#define L_  8192
#define PC  1024          // P*C
#define LS  4096          // L/2

// Scratch (static device allocations; no runtime alloc allowed)
__device__ float g_sc[B_ * PC * LS];   // sc_flat  [B][PC][LS]  128 MB
__device__ float g_y [B_ * PC * LS];   // sc_mixed [B][PC][LS]  128 MB
__device__ float g_mean[PC];
__device__ float g_rstd[PC];

// ---------------------------------------------------------------------------
// Pass 1: Haar analysis. Each thread consumes 4 consecutive input samples.
// Writes sc (in GEMM layout [B][PC][LS]) and the SECOND half of the output,
// which depends only on the detail coefficients:
//   out[4096+2m]   = S00*d0 + S01*d1
//   out[4096+2m+1] = S10*d0 + S11*d1,   d_i from A row 1.
// ---------------------------------------------------------------------------
__global__ void analysis_kernel(const float* __restrict__ xs,
                                const float* __restrict__ A,
                                const float* __restrict__ S,
                                float* __restrict__ out)
{
    int tid = blockIdx.x * blockDim.x + threadIdx.x;   // < P*B*C*2048
    int m = tid & 2047;
    int c = (tid >> 11) & 127;
    int b = (tid >> 18) & 7;
    int p = tid >> 21;

    float a00 = A[0], a01 = A[1], a10 = A[2], a11 = A[3];
    float s00 = S[0], s01 = S[1], s10 = S[2], s11 = S[3];

    long xoff = ((long)((p * B_ + b) * C_ + c) << 13) + (m << 2);
    float4 x4 = *(const float4*)(xs + xoff);

    float sc0 = a00 * x4.x + a01 * x4.y;
    float sc1 = a00 * x4.z + a01 * x4.w;
    float d0  = a10 * x4.x + a11 * x4.y;
    float d1  = a10 * x4.z + a11 * x4.w;

    int j = p * C_ + c;
    *(float2*)(g_sc + ((b * PC + j) * LS + (m << 1))) = make_float2(sc0, sc1);

    float o0 = s00 * d0 + s01 * d1;
    float o1 = s10 * d0 + s11 * d1;
    *(float2*)(out + ((long)((p * B_ + b) * C_ + c) << 13) + LS + (m << 1))
        = make_float2(o0, o1);
}

// ---------------------------------------------------------------------------
// Pass 2: batched SGEMM  Y[b] = W(1024x1024) @ X[b](1024x4096), fp32.
// 128x128 block tile, BK=8, 8x8 microtile, 256 threads, double-buffered smem.
// ---------------------------------------------------------------------------
#define BM 128
#define BN 128
#define BK 8

__global__ __launch_bounds__(256)
void sgemm_kernel(const float* __restrict__ W)
{
    __shared__ float As[2][BK][BM];
    __shared__ float Bs[2][BK][BN];

    int bx = blockIdx.x, by = blockIdx.y, bz = blockIdx.z;
    const float* Wp = W    + by * BM * PC;
    const float* Xp = g_sc + bz * PC * LS + bx * BN;
    float*       Yp = g_y  + bz * PC * LS + by * BM * LS + bx * BN;

    int tid = threadIdx.x;
    int lm = tid >> 1;            // A-tile row (0..127)
    int lk = (tid & 1) << 2;      // A-tile k   (0 or 4)
    int bk = tid >> 5;            // B-tile row (0..7)
    int bn = (tid & 31) << 2;     // B-tile col (0..124)
    int ty = tid >> 4, tx = tid & 15;

    float acc[8][8];
    #pragma unroll
    for (int i = 0; i < 8; i++)
        #pragma unroll
        for (int j = 0; j < 8; j++) acc[i][j] = 0.f;

    // preload tile 0
    float4 a4 = *(const float4*)(Wp + lm * PC + lk);
    float4 b4 = *(const float4*)(Xp + bk * LS + bn);
    As[0][lk + 0][lm] = a4.x; As[0][lk + 1][lm] = a4.y;
    As[0][lk + 2][lm] = a4.z; As[0][lk + 3][lm] = a4.w;
    *(float4*)&Bs[0][bk][bn] = b4;
    __syncthreads();

    const int NT = PC / BK;       // 128 k-tiles
    for (int kt = 0; kt < NT; ++kt) {
        int cur = kt & 1, nxt = cur ^ 1;
        if (kt + 1 < NT) {
            a4 = *(const float4*)(Wp + lm * PC + (kt + 1) * BK + lk);
            b4 = *(const float4*)(Xp + ((kt + 1) * BK + bk) * LS + bn);
        }
        #pragma unroll
        for (int k = 0; k < BK; ++k) {
            float ra[8], rb[8];
            *(float4*)&ra[0] = *(float4*)&As[cur][k][ty * 8];
            *(float4*)&ra[4] = *(float4*)&As[cur][k][ty * 8 + 4];
            *(float4*)&rb[0] = *(float4*)&Bs[cur][k][tx * 8];
            *(float4*)&rb[4] = *(float4*)&Bs[cur][k][tx * 8 + 4];
            #pragma unroll
            for (int i = 0; i < 8; i++)
                #pragma unroll
                for (int j = 0; j < 8; j++)
                    acc[i][j] += ra[i] * rb[j];
        }
        if (kt + 1 < NT) {
            As[nxt][lk + 0][lm] = a4.x; As[nxt][lk + 1][lm] = a4.y;
            As[nxt][lk + 2][lm] = a4.z; As[nxt][lk + 3][lm] = a4.w;
            *(float4*)&Bs[nxt][bk][bn] = b4;
        }
        __syncthreads();
    }

    #pragma unroll
    for (int i = 0; i < 8; i++) {
        float4 v0 = make_float4(acc[i][0], acc[i][1], acc[i][2], acc[i][3]);
        float4 v1 = make_float4(acc[i][4], acc[i][5], acc[i][6], acc[i][7]);
        *(float4*)(Yp + (ty * 8 + i) * LS + tx * 8)     = v0;
        *(float4*)(Yp + (ty * 8 + i) * LS + tx * 8 + 4) = v1;
    }
}

// ---------------------------------------------------------------------------
// Pass 3: BatchNorm statistics per channel j over (B, Ls) = 32768 samples.
// Biased variance, matching the reference.
// ---------------------------------------------------------------------------
__global__ void bn_stats_kernel()
{
    int j = blockIdx.x;
    float s = 0.f, q = 0.f;
    for (int idx = threadIdx.x; idx < B_ * LS; idx += blockDim.x) {
        int b = idx >> 12;           // LS = 4096
        int l = idx & (LS - 1);
        float v = g_y[(b * PC + j) * LS + l];
        s += v;
        q += v * v;
    }
    #pragma unroll
    for (int o = 16; o > 0; o >>= 1) {
        s += __shfl_down_sync(0xffffffffu, s, o);
        q += __shfl_down_sync(0xffffffffu, q, o);
    }
    __shared__ float sh_s[8], sh_q[8];
    int w = threadIdx.x >> 5, lane = threadIdx.x & 31;
    if (lane == 0) { sh_s[w] = s; sh_q[w] = q; }
    __syncthreads();
    if (threadIdx.x == 0) {
        float S = 0.f, Q = 0.f;
        #pragma unroll
        for (int i = 0; i < 8; i++) { S += sh_s[i]; Q += sh_q[i]; }
        const float inv = 1.f / (float)(B_ * LS);
        float mean = S * inv;
        float var  = Q * inv - mean * mean;
        g_mean[j] = mean;
        g_rstd[j] = rsqrtf(var + 1e-5f);
    }
}

// ---------------------------------------------------------------------------
// Pass 4: BN + exact GELU + Haar synthesis -> FIRST half of the output.
//   out[2m]   = S00*a0 + S01*a1
//   out[2m+1] = S10*a0 + S11*a1,   a_i = gelu(gamma*norm(y_i)+beta)
// ---------------------------------------------------------------------------
__device__ __forceinline__ float gelu_exact(float z)
{
    return 0.5f * z * (1.0f + erff(z * 0.70710678118654752440f));
}

__global__ void synth_kernel(const float* __restrict__ S,
                             const float* __restrict__ gamma,
                             const float* __restrict__ beta,
                             float* __restrict__ out)
{
    int tid = blockIdx.x * blockDim.x + threadIdx.x;   // < P*B*C*2048
    int m = tid & 2047;
    int c = (tid >> 11) & 127;
    int b = (tid >> 18) & 7;
    int p = tid >> 21;

    int j = p * C_ + c;
    float2 y = *(const float2*)(g_y + ((b * PC + j) * LS + (m << 1)));

    float mean = g_mean[j], rstd = g_rstd[j];
    float g = gamma[j], be = beta[j];
    float s00 = S[0], s01 = S[1], s10 = S[2], s11 = S[3];

    float z0 = (y.x - mean) * rstd * g + be;
    float z1 = (y.y - mean) * rstd * g + be;
    float a0 = gelu_exact(z0);
    float a1 = gelu_exact(z1);

    float o0 = s00 * a0 + s01 * a1;
    float o1 = s10 * a0 + s11 * a1;
    *(float2*)(out + ((long)((p * B_ + b) * C_ + c) << 13) + (m << 1))
        = make_float2(o0, o1);
}

// ---------------------------------------------------------------------------
extern "C" void kernel_launch(void* const* d_in, const int* in_sizes, int n_in,
                              void* d_out, int out_size)
{
    const float* xs    = (const float*)d_in[0];
    const float* A     = (const float*)d_in[1];
    const float* S     = (const float*)d_in[2];
    const float* W     = (const float*)d_in[3];
    const float* gamma = (const float*)d_in[4];
    const float* beta  = (const float*)d_in[5];
    float* out = (float*)d_out;

    int total = P_ * B_ * C_ * (L_ / 4);               // 16,777,216 threads
    analysis_kernel<<<total / 256, 256>>>(xs, A, S, out);

    dim3 g(LS / BN, PC / BM, B_);                      // (32, 8, 8)
    sgemm_kernel<<<g, 256>>>(W);

    bn_stats_kernel<<<PC, 256>>>();

    synth_kernel<<<total / 256, 256>>>(S, gamma, beta, out);
}

// round 3
// speedup vs baseline: 2.4610x; 2.4610x over previous
#include <cuda_runtime.h>
#include <cuda_bf16.h>
#include <cstdint>

#define P_  8
#define B_  8
#define C_  128
#define L_  8192
#define PC  1024          // P*C
#define LS  4096          // L/2

// ---------------------------------------------------------------------------
// Static device scratch (no runtime allocation allowed)
// ---------------------------------------------------------------------------
__device__ __align__(16) __nv_bfloat16 g_Dhi[PC * PC];            //  2 MB  W - I (hi)
__device__ __align__(16) __nv_bfloat16 g_Dlo[PC * PC];            //  2 MB  W - I (lo)
__device__ __align__(16) __nv_bfloat16 g_Xt [(long)B_ * LS * PC]; // 64 MB  sc^T [b][l][j]
__device__ __align__(16) float         g_sc [(long)B_ * PC * LS]; //128 MB  sc   [b][j][l]
__device__ __align__(16) float         g_y  [(long)B_ * PC * LS]; //128 MB  y    [b][j][l]
__device__ float g_mean[PC];
__device__ float g_rstd[PC];

__device__ __forceinline__ uint32_t smem_u32(const void* p) {
    uint32_t a;
    asm("{ .reg .u64 t; cvta.to.shared.u64 t, %1; cvt.u32.u64 %0, t; }" : "=r"(a) : "l"(p));
    return a;
}

#define CP_ASYNC16(saddr, gptr) \
    asm volatile("cp.async.cg.shared.global [%0], [%1], 16;" :: "r"(saddr), "l"(gptr))
#define CP_COMMIT() asm volatile("cp.async.commit_group;")
#define CP_WAIT1()  asm volatile("cp.async.wait_group 1;")

#define LDSM4(r0, r1, r2, r3, addr) \
    asm volatile("ldmatrix.sync.aligned.m8n8.x4.shared.b16 {%0,%1,%2,%3}, [%4];" \
        : "=r"(r0), "=r"(r1), "=r"(r2), "=r"(r3) : "r"(addr))

#define MMA16816(acc, a, b) \
    asm volatile("mma.sync.aligned.m16n8k16.row.col.f32.bf16.bf16.f32 " \
        "{%0,%1,%2,%3}, {%4,%5,%6,%7}, {%8,%9}, {%0,%1,%2,%3};" \
        : "+f"((acc)[0]), "+f"((acc)[1]), "+f"((acc)[2]), "+f"((acc)[3]) \
        : "r"((a)[0]), "r"((a)[1]), "r"((a)[2]), "r"((a)[3]), \
          "r"((b)[0]), "r"((b)[1]))

// ---------------------------------------------------------------------------
// Pass 1: Haar analysis. Writes detail-half of output directly, exact fp32
// sc into g_sc [b][j][l], and bf16 sc TRANSPOSED into g_Xt [b][l][j].
// ---------------------------------------------------------------------------
__global__ __launch_bounds__(256) void analysis_kernel(
    const float* __restrict__ xs, const float* __restrict__ A,
    const float* __restrict__ S, float* __restrict__ out)
{
    __shared__ __nv_bfloat16 sh[64][33];
    const int t = threadIdx.x;
    const int b = blockIdx.z;
    const int J0 = blockIdx.y * 32;
    const int M0 = blockIdx.x * 32;

    const float a00 = A[0], a01 = A[1], a10 = A[2], a11 = A[3];
    const float s00 = S[0], s01 = S[1], s10 = S[2], s11 = S[3];

    const int m  = t & 31;
    const int jr = t >> 5;
    #pragma unroll
    for (int jl = 0; jl < 4; jl++) {
        int jj = jr + 8 * jl;
        int j = J0 + jj;
        int p = j >> 7, c = j & 127;
        long base = ((long)((p * B_ + b) * C_ + c)) << 13;   // *8192
        float4 x4 = *(const float4*)(xs + base + 4 * (M0 + m));
        float sc0 = a00 * x4.x + a01 * x4.y;
        float sc1 = a00 * x4.z + a01 * x4.w;
        float d0  = a10 * x4.x + a11 * x4.y;
        float d1  = a10 * x4.z + a11 * x4.w;
        *(float2*)(out + base + LS + 2 * (M0 + m))
            = make_float2(s00 * d0 + s01 * d1, s10 * d0 + s11 * d1);
        *(float2*)(g_sc + ((long)(b * PC + j)) * LS + 2 * (M0 + m))
            = make_float2(sc0, sc1);
        sh[2 * m][jj]     = __float2bfloat16(sc0);
        sh[2 * m + 1][jj] = __float2bfloat16(sc1);
    }
    __syncthreads();
    const int jj = t & 31;
    const int nr = t >> 5;
    #pragma unroll
    for (int i = 0; i < 8; i++) {
        int n = nr + 8 * i;
        g_Xt[((long)(b * LS + 2 * M0 + n)) * PC + J0 + jj] = sh[n][jj];
    }
}

// ---------------------------------------------------------------------------
// D = W - I split into bf16 hi + lo
// ---------------------------------------------------------------------------
__global__ void wsplit_kernel(const float* __restrict__ W)
{
    int i = blockIdx.x * 256 + threadIdx.x;
    int row = i >> 10, col = i & 1023;
    float d = W[i] - (row == col ? 1.0f : 0.0f);
    __nv_bfloat16 h = __float2bfloat16(d);
    g_Dhi[i] = h;
    g_Dlo[i] = __float2bfloat16(d - __bfloat162float(h));
}

// ---------------------------------------------------------------------------
// Pass 2: HMMA GEMM  y = sc + D@sc  (D split hi+lo => K-extended to 2048).
// CTA tile 128(M=j') x 256(N=l), 256 threads (8 warps, 2x4 of 64x64).
// 3-stage cp.async pipeline, BK=32, xor-swizzled smem, ldmatrix + mma.16816.
// ---------------------------------------------------------------------------
#define BKB 64                 // bytes per smem row (32 bf16)
#define STAGE_B 24576          // A(8KB) + B(16KB)
#define GEMM_SMEM (3 * STAGE_B)

__device__ __forceinline__ void load_stage(uint32_t sbase, int stg,
    const __nv_bfloat16* __restrict__ Asrc,
    const __nv_bfloat16* __restrict__ Bsrc, int kk, int t)
{
    uint32_t sa = sbase + stg * STAGE_B;
    #pragma unroll
    for (int i = 0; i < 2; i++) {                     // A: 128 rows x 4 chunks
        int idx = t + 256 * i;
        int row = idx >> 2, c = idx & 3;
        const __nv_bfloat16* g = Asrc + (long)row * PC + kk * 32 + c * 8;
        uint32_t s = sa + row * BKB + (((c ^ ((row >> 1) & 3))) << 4);
        CP_ASYNC16(s, g);
    }
    #pragma unroll
    for (int i = 0; i < 4; i++) {                     // B: 256 rows x 4 chunks
        int idx = t + 256 * i;
        int row = idx >> 2, c = idx & 3;
        const __nv_bfloat16* g = Bsrc + (long)row * PC + kk * 32 + c * 8;
        uint32_t s = sa + 8192 + row * BKB + (((c ^ ((row >> 1) & 3))) << 4);
        CP_ASYNC16(s, g);
    }
}

__global__ void __launch_bounds__(256, 1) gemm_kernel()
{
    extern __shared__ char smem[];
    const uint32_t sbase = smem_u32(smem);
    const int t    = threadIdx.x;
    const int lane = t & 31;
    const int wid  = t >> 5;
    const int wm   = wid >> 2;            // 0..1
    const int wn   = wid & 3;             // 0..3
    const int m0   = blockIdx.x * 128;
    const int n0   = blockIdx.y * 256;
    const int b    = blockIdx.z;

    const __nv_bfloat16* Ahi = g_Dhi + (long)m0 * PC;
    const __nv_bfloat16* Alo = g_Dlo + (long)m0 * PC;
    const __nv_bfloat16* Bsrc = g_Xt + ((long)b * LS + n0) * PC;

    // per-lane ldmatrix constants
    const int rA  = lane & 15;
    const int hkA = lane >> 4;
    const int cA  = (rA >> 1) & 3;
    const uint32_t offA = (uint32_t)(wm * 64 + rA) * BKB;
    const int rB  = (lane & 7) | ((lane >> 4) << 3);
    const int hkB = (lane >> 3) & 1;
    const int cB  = (rB >> 1) & 3;
    const uint32_t offB = 8192u + (uint32_t)(wn * 64 + rB) * BKB;

    float acc[4][8][4];
    #pragma unroll
    for (int mi = 0; mi < 4; mi++)
        #pragma unroll
        for (int ni = 0; ni < 8; ni++)
            #pragma unroll
            for (int q = 0; q < 4; q++) acc[mi][ni][q] = 0.f;

    // prologue: stages 0, 1  (chunk kt: term = kt>>5, kk = kt&31)
    load_stage(sbase, 0, Ahi, Bsrc, 0, t); CP_COMMIT();
    load_stage(sbase, 1, Ahi, Bsrc, 1, t); CP_COMMIT();

    int stg = 0;
    for (int kt = 0; kt < 64; kt++) {
        CP_WAIT1();
        __syncthreads();
        {
            int kn = kt + 2;
            if (kn < 64) {
                int stn = stg + 2; if (stn >= 3) stn -= 3;
                load_stage(sbase, stn, (kn < 32) ? Ahi : Alo, Bsrc, kn & 31, t);
            }
            CP_COMMIT();
        }
        uint32_t sa = sbase + stg * STAGE_B;
        #pragma unroll
        for (int s2 = 0; s2 < 2; s2++) {
            uint32_t a[4][4], bf[8][2];
            #pragma unroll
            for (int mi = 0; mi < 4; mi++) {
                uint32_t addr = sa + offA + mi * (16 * BKB)
                              + (uint32_t)(((2 * s2 + hkA) ^ cA) << 4);
                LDSM4(a[mi][0], a[mi][1], a[mi][2], a[mi][3], addr);
            }
            #pragma unroll
            for (int p = 0; p < 4; p++) {
                uint32_t addr = sa + offB + p * (16 * BKB)
                              + (uint32_t)(((2 * s2 + hkB) ^ cB) << 4);
                LDSM4(bf[2 * p][0], bf[2 * p][1], bf[2 * p + 1][0], bf[2 * p + 1][1], addr);
            }
            #pragma unroll
            for (int mi = 0; mi < 4; mi++)
                #pragma unroll
                for (int ni = 0; ni < 8; ni++)
                    MMA16816(acc[mi][ni], a[mi], bf[ni]);
        }
        if (++stg == 3) stg = 0;
        __syncthreads();
    }

    // Epilogue: y = sc + acc
    const int r0 = m0 + wm * 64 + (lane >> 2);
    const int c0 = n0 + wn * 64 + (lane & 3) * 2;
    #pragma unroll
    for (int mi = 0; mi < 4; mi++) {
        int rowa = r0 + mi * 16;
        int rowb = rowa + 8;
        long oa = ((long)b * PC + rowa) * LS + c0;
        long ob = ((long)b * PC + rowb) * LS + c0;
        #pragma unroll
        for (int ni = 0; ni < 8; ni++) {
            float2 sa2 = *(const float2*)(g_sc + oa + ni * 8);
            float2 sb2 = *(const float2*)(g_sc + ob + ni * 8);
            *(float2*)(g_y + oa + ni * 8)
                = make_float2(acc[mi][ni][0] + sa2.x, acc[mi][ni][1] + sa2.y);
            *(float2*)(g_y + ob + ni * 8)
                = make_float2(acc[mi][ni][2] + sb2.x, acc[mi][ni][3] + sb2.y);
        }
    }
}

// ---------------------------------------------------------------------------
// Pass 3: BatchNorm statistics per channel j over (B, Ls) (biased variance)
// ---------------------------------------------------------------------------
__global__ void bn_stats_kernel()
{
    int j = blockIdx.x;
    float s = 0.f, q = 0.f;
    for (int idx = threadIdx.x; idx < B_ * LS; idx += blockDim.x) {
        int b = idx >> 12;
        int l = idx & (LS - 1);
        float v = g_y[(b * PC + j) * LS + l];
        s += v;
        q += v * v;
    }
    #pragma unroll
    for (int o = 16; o > 0; o >>= 1) {
        s += __shfl_down_sync(0xffffffffu, s, o);
        q += __shfl_down_sync(0xffffffffu, q, o);
    }
    __shared__ float sh_s[8], sh_q[8];
    int w = threadIdx.x >> 5, lane = threadIdx.x & 31;
    if (lane == 0) { sh_s[w] = s; sh_q[w] = q; }
    __syncthreads();
    if (threadIdx.x == 0) {
        float S = 0.f, Q = 0.f;
        #pragma unroll
        for (int i = 0; i < 8; i++) { S += sh_s[i]; Q += sh_q[i]; }
        const float inv = 1.f / (float)(B_ * LS);
        float mean = S * inv;
        float var  = Q * inv - mean * mean;
        g_mean[j] = mean;
        g_rstd[j] = rsqrtf(var + 1e-5f);
    }
}

// ---------------------------------------------------------------------------
// Pass 4: BN + exact GELU + Haar synthesis -> FIRST half of the output
// ---------------------------------------------------------------------------
__device__ __forceinline__ float gelu_exact(float z)
{
    return 0.5f * z * (1.0f + erff(z * 0.70710678118654752440f));
}

__global__ void synth_kernel(const float* __restrict__ S,
                             const float* __restrict__ gamma,
                             const float* __restrict__ beta,
                             float* __restrict__ out)
{
    int tid = blockIdx.x * blockDim.x + threadIdx.x;
    int m = tid & 2047;
    int c = (tid >> 11) & 127;
    int b = (tid >> 18) & 7;
    int p = tid >> 21;

    int j = p * C_ + c;
    float2 y = *(const float2*)(g_y + ((b * PC + j) * LS + (m << 1)));

    float mean = g_mean[j], rstd = g_rstd[j];
    float g = gamma[j], be = beta[j];
    float s00 = S[0], s01 = S[1], s10 = S[2], s11 = S[3];

    float z0 = (y.x - mean) * rstd * g + be;
    float z1 = (y.y - mean) * rstd * g + be;
    float a0 = gelu_exact(z0);
    float a1 = gelu_exact(z1);

    *(float2*)(out + ((long)((p * B_ + b) * C_ + c) << 13) + (m << 1))
        = make_float2(s00 * a0 + s01 * a1, s10 * a0 + s11 * a1);
}

// ---------------------------------------------------------------------------
extern "C" void kernel_launch(void* const* d_in, const int* in_sizes, int n_in,
                              void* d_out, int out_size)
{
    const float* xs    = (const float*)d_in[0];
    const float* A     = (const float*)d_in[1];
    const float* S     = (const float*)d_in[2];
    const float* W     = (const float*)d_in[3];
    const float* gamma = (const float*)d_in[4];
    const float* beta  = (const float*)d_in[5];
    float* out = (float*)d_out;

    static int smem_set = 0;
    if (!smem_set) {
        cudaFuncSetAttribute(gemm_kernel,
                             cudaFuncAttributeMaxDynamicSharedMemorySize, GEMM_SMEM);
        smem_set = 1;
    }

    analysis_kernel<<<dim3(64, 32, 8), 256>>>(xs, A, S, out);
    wsplit_kernel<<<PC * PC / 256, 256>>>(W);
    gemm_kernel<<<dim3(8, 16, 8), 256, GEMM_SMEM>>>();
    bn_stats_kernel<<<PC, 256>>>();
    synth_kernel<<<P_ * B_ * C_ * (L_ / 4) / 256, 256>>>(S, gamma, beta, out);
}

// round 4
// speedup vs baseline: 2.8039x; 1.1393x over previous
#include <cuda_runtime.h>
#include <cuda_bf16.h>
#include <cstdint>

#define P_  8
#define B_  8
#define C_  128
#define L_  8192
#define PC  1024          // P*C
#define LS  4096          // L/2

// ---------------------------------------------------------------------------
// Static device scratch (no runtime allocation allowed)
// ---------------------------------------------------------------------------
__device__ __align__(16) __nv_bfloat16 g_Dhi[PC * PC];            //  2 MB  W - I (hi)
__device__ __align__(16) __nv_bfloat16 g_Dlo[PC * PC];            //  2 MB  W - I (lo)
__device__ __align__(16) __nv_bfloat16 g_Xt [(long)B_ * LS * PC]; // 64 MB  sc^T [b][l][j]
__device__ __align__(16) float         g_sc [(long)B_ * PC * LS]; //128 MB  sc   [b][j][l]
__device__ __align__(16) float         g_y  [(long)B_ * PC * LS]; //128 MB  y    [b][j][l]
__device__ float g_pS[PC * 128];   // per-channel partial sums   [j][slot]
__device__ float g_pQ[PC * 128];   // per-channel partial sumsq  [j][slot]
__device__ float g_mean[PC];
__device__ float g_rstd[PC];

__device__ __forceinline__ uint32_t smem_u32(const void* p) {
    uint32_t a;
    asm("{ .reg .u64 t; cvta.to.shared.u64 t, %1; cvt.u32.u64 %0, t; }" : "=r"(a) : "l"(p));
    return a;
}

#define CP_ASYNC16(saddr, gptr) \
    asm volatile("cp.async.cg.shared.global [%0], [%1], 16;" :: "r"(saddr), "l"(gptr))
#define CP_COMMIT() asm volatile("cp.async.commit_group;")
#define CP_WAIT1()  asm volatile("cp.async.wait_group 1;")

#define LDSM4(r0, r1, r2, r3, addr) \
    asm volatile("ldmatrix.sync.aligned.m8n8.x4.shared.b16 {%0,%1,%2,%3}, [%4];" \
        : "=r"(r0), "=r"(r1), "=r"(r2), "=r"(r3) : "r"(addr))

#define MMA16816(acc, a, b) \
    asm volatile("mma.sync.aligned.m16n8k16.row.col.f32.bf16.bf16.f32 " \
        "{%0,%1,%2,%3}, {%4,%5,%6,%7}, {%8,%9}, {%0,%1,%2,%3};" \
        : "+f"((acc)[0]), "+f"((acc)[1]), "+f"((acc)[2]), "+f"((acc)[3]) \
        : "r"((a)[0]), "r"((a)[1]), "r"((a)[2]), "r"((a)[3]), \
          "r"((b)[0]), "r"((b)[1]))

// ---------------------------------------------------------------------------
// Pass 1: Haar analysis. Writes detail-half of output directly, exact fp32
// sc into g_sc [b][j][l], and bf16 sc TRANSPOSED into g_Xt [b][l][j].
// ---------------------------------------------------------------------------
__global__ __launch_bounds__(256) void analysis_kernel(
    const float* __restrict__ xs, const float* __restrict__ A,
    const float* __restrict__ S, float* __restrict__ out)
{
    __shared__ __nv_bfloat16 sh[64][33];
    const int t = threadIdx.x;
    const int b = blockIdx.z;
    const int J0 = blockIdx.y * 32;
    const int M0 = blockIdx.x * 32;

    const float a00 = A[0], a01 = A[1], a10 = A[2], a11 = A[3];
    const float s00 = S[0], s01 = S[1], s10 = S[2], s11 = S[3];

    const int m  = t & 31;
    const int jr = t >> 5;
    #pragma unroll
    for (int jl = 0; jl < 4; jl++) {
        int jj = jr + 8 * jl;
        int j = J0 + jj;
        int p = j >> 7, c = j & 127;
        long base = ((long)((p * B_ + b) * C_ + c)) << 13;   // *8192
        float4 x4 = *(const float4*)(xs + base + 4 * (M0 + m));
        float sc0 = a00 * x4.x + a01 * x4.y;
        float sc1 = a00 * x4.z + a01 * x4.w;
        float d0  = a10 * x4.x + a11 * x4.y;
        float d1  = a10 * x4.z + a11 * x4.w;
        *(float2*)(out + base + LS + 2 * (M0 + m))
            = make_float2(s00 * d0 + s01 * d1, s10 * d0 + s11 * d1);
        *(float2*)(g_sc + ((long)(b * PC + j)) * LS + 2 * (M0 + m))
            = make_float2(sc0, sc1);
        sh[2 * m][jj]     = __float2bfloat16(sc0);
        sh[2 * m + 1][jj] = __float2bfloat16(sc1);
    }
    __syncthreads();
    const int jj = t & 31;
    const int nr = t >> 5;
    #pragma unroll
    for (int i = 0; i < 8; i++) {
        int n = nr + 8 * i;
        g_Xt[((long)(b * LS + 2 * M0 + n)) * PC + J0 + jj] = sh[n][jj];
    }
}

// ---------------------------------------------------------------------------
// D = W - I split into bf16 hi + lo
// ---------------------------------------------------------------------------
__global__ void wsplit_kernel(const float* __restrict__ W)
{
    int i = blockIdx.x * 256 + threadIdx.x;
    int row = i >> 10, col = i & 1023;
    float d = W[i] - (row == col ? 1.0f : 0.0f);
    __nv_bfloat16 h = __float2bfloat16(d);
    g_Dhi[i] = h;
    g_Dlo[i] = __float2bfloat16(d - __bfloat162float(h));
}

// ---------------------------------------------------------------------------
// Pass 2: HMMA GEMM  y = sc + Dhi@sc + Dlo@sc, SHARED B operand per stage.
// CTA 128(M) x 256(N), 256 threads (2x4 warps of 64x64), 32 K-iterations of
// BK=32, 3-stage cp.async pipeline {Ahi|Alo|B}, one __syncthreads per iter.
// Epilogue: y = sc + acc, plus deterministic per-row BN partial sums.
// ---------------------------------------------------------------------------
#define STAGE_B 32768          // Ahi 8KB | Alo 8KB | B 16KB
#define GEMM_SMEM (3 * STAGE_B)

__device__ __forceinline__ void load_stage(uint32_t sbase, int stg,
    const __nv_bfloat16* __restrict__ Ahi,
    const __nv_bfloat16* __restrict__ Alo,
    const __nv_bfloat16* __restrict__ Bsrc, int kk, int t)
{
    uint32_t sa = sbase + stg * STAGE_B;
    #pragma unroll
    for (int i = 0; i < 2; i++) {                     // A hi+lo: 128 rows x 4 chunks
        int idx = t + 256 * i;
        int row = idx >> 2, c = idx & 3;
        uint32_t sw = (uint32_t)((c ^ ((row >> 1) & 3)) << 4);
        const __nv_bfloat16* gh = Ahi + (long)row * PC + kk * 32 + c * 8;
        const __nv_bfloat16* gl = Alo + (long)row * PC + kk * 32 + c * 8;
        CP_ASYNC16(sa + row * 64 + sw, gh);
        CP_ASYNC16(sa + 8192 + row * 64 + sw, gl);
    }
    #pragma unroll
    for (int i = 0; i < 4; i++) {                     // B: 256 rows x 4 chunks
        int idx = t + 256 * i;
        int row = idx >> 2, c = idx & 3;
        uint32_t sw = (uint32_t)((c ^ ((row >> 1) & 3)) << 4);
        const __nv_bfloat16* g = Bsrc + (long)row * PC + kk * 32 + c * 8;
        CP_ASYNC16(sa + 16384 + row * 64 + sw, g);
    }
}

__global__ void __launch_bounds__(256, 1) gemm_kernel()
{
    extern __shared__ char smem[];
    const uint32_t sbase = smem_u32(smem);
    const int t    = threadIdx.x;
    const int lane = t & 31;
    const int wid  = t >> 5;
    const int wm   = wid >> 2;            // 0..1
    const int wn   = wid & 3;             // 0..3
    const int m0   = blockIdx.x * 128;
    const int n0   = blockIdx.y * 256;
    const int b    = blockIdx.z;

    const __nv_bfloat16* Ahi = g_Dhi + (long)m0 * PC;
    const __nv_bfloat16* Alo = g_Dlo + (long)m0 * PC;
    const __nv_bfloat16* Bsrc = g_Xt + ((long)b * LS + n0) * PC;

    // per-lane ldmatrix constants
    const int rA  = lane & 15;
    const int hkA = lane >> 4;
    const int cA  = (rA >> 1) & 3;
    const uint32_t offA = (uint32_t)(wm * 64 + rA) * 64;
    const int rB  = (lane & 7) | ((lane >> 4) << 3);
    const int hkB = (lane >> 3) & 1;
    const int cB  = (rB >> 1) & 3;
    const uint32_t offB = 16384u + (uint32_t)(wn * 64 + rB) * 64;

    float acc[4][8][4];
    #pragma unroll
    for (int mi = 0; mi < 4; mi++)
        #pragma unroll
        for (int ni = 0; ni < 8; ni++)
            #pragma unroll
            for (int q = 0; q < 4; q++) acc[mi][ni][q] = 0.f;

    load_stage(sbase, 0, Ahi, Alo, Bsrc, 0, t); CP_COMMIT();
    load_stage(sbase, 1, Ahi, Alo, Bsrc, 1, t); CP_COMMIT();

    int stg = 0;
    for (int kt = 0; kt < 32; kt++) {
        CP_WAIT1();
        __syncthreads();
        {
            int kn = kt + 2;
            if (kn < 32) {
                int stn = stg + 2; if (stn >= 3) stn -= 3;
                load_stage(sbase, stn, Ahi, Alo, Bsrc, kn, t);
            }
            CP_COMMIT();
        }
        uint32_t sa = sbase + stg * STAGE_B;
        #pragma unroll
        for (int s2 = 0; s2 < 2; s2++) {
            uint32_t bf[8][2];
            #pragma unroll
            for (int p = 0; p < 4; p++) {
                uint32_t addr = sa + offB + p * (16 * 64)
                              + (uint32_t)(((2 * s2 + hkB) ^ cB) << 4);
                LDSM4(bf[2 * p][0], bf[2 * p][1], bf[2 * p + 1][0], bf[2 * p + 1][1], addr);
            }
            uint32_t a[4][4];
            #pragma unroll
            for (int mi = 0; mi < 4; mi++) {
                uint32_t addr = sa + offA + mi * (16 * 64)
                              + (uint32_t)(((2 * s2 + hkA) ^ cA) << 4);
                LDSM4(a[mi][0], a[mi][1], a[mi][2], a[mi][3], addr);
            }
            #pragma unroll
            for (int mi = 0; mi < 4; mi++)
                #pragma unroll
                for (int ni = 0; ni < 8; ni++)
                    MMA16816(acc[mi][ni], a[mi], bf[ni]);
            #pragma unroll
            for (int mi = 0; mi < 4; mi++) {
                uint32_t addr = sa + 8192 + offA + mi * (16 * 64)
                              + (uint32_t)(((2 * s2 + hkA) ^ cA) << 4);
                LDSM4(a[mi][0], a[mi][1], a[mi][2], a[mi][3], addr);
            }
            #pragma unroll
            for (int mi = 0; mi < 4; mi++)
                #pragma unroll
                for (int ni = 0; ni < 8; ni++)
                    MMA16816(acc[mi][ni], a[mi], bf[ni]);
        }
        if (++stg == 3) stg = 0;
    }

    // ------------------- Epilogue: y = sc + acc, BN partials ---------------
    __syncthreads();                       // smem stages -> scratch
    float* sS = (float*)smem;              // [128][4]
    float* sQ = (float*)smem + 512;        // [128][4]

    const int rl = wm * 64 + (lane >> 2);  // local row base
    const int c0 = n0 + wn * 64 + (lane & 3) * 2;
    #pragma unroll
    for (int mi = 0; mi < 4; mi++) {
        int rla = rl + mi * 16, rlb = rla + 8;
        long oa = ((long)b * PC + m0 + rla) * LS + c0;
        long ob = ((long)b * PC + m0 + rlb) * LS + c0;
        float sa_ = 0.f, qa_ = 0.f, sb_ = 0.f, qb_ = 0.f;
        #pragma unroll
        for (int ni = 0; ni < 8; ni++) {
            float2 v0 = *(const float2*)(g_sc + oa + ni * 8);
            float2 v1 = *(const float2*)(g_sc + ob + ni * 8);
            float y0 = acc[mi][ni][0] + v0.x, y1 = acc[mi][ni][1] + v0.y;
            float y2 = acc[mi][ni][2] + v1.x, y3 = acc[mi][ni][3] + v1.y;
            *(float2*)(g_y + oa + ni * 8) = make_float2(y0, y1);
            *(float2*)(g_y + ob + ni * 8) = make_float2(y2, y3);
            sa_ += y0 + y1; qa_ += y0 * y0 + y1 * y1;
            sb_ += y2 + y3; qb_ += y2 * y2 + y3 * y3;
        }
        sa_ += __shfl_xor_sync(0xffffffffu, sa_, 1);
        sa_ += __shfl_xor_sync(0xffffffffu, sa_, 2);
        qa_ += __shfl_xor_sync(0xffffffffu, qa_, 1);
        qa_ += __shfl_xor_sync(0xffffffffu, qa_, 2);
        sb_ += __shfl_xor_sync(0xffffffffu, sb_, 1);
        sb_ += __shfl_xor_sync(0xffffffffu, sb_, 2);
        qb_ += __shfl_xor_sync(0xffffffffu, qb_, 1);
        qb_ += __shfl_xor_sync(0xffffffffu, qb_, 2);
        if ((lane & 3) == 0) {
            sS[rla * 4 + wn] = sa_; sQ[rla * 4 + wn] = qa_;
            sS[rlb * 4 + wn] = sb_; sQ[rlb * 4 + wn] = qb_;
        }
    }
    __syncthreads();
    if (t < 128) {
        float s = sS[t * 4] + sS[t * 4 + 1] + sS[t * 4 + 2] + sS[t * 4 + 3];
        float q = sQ[t * 4] + sQ[t * 4 + 1] + sQ[t * 4 + 2] + sQ[t * 4 + 3];
        int slot = b * 16 + blockIdx.y;    // 128 slots per channel
        g_pS[(m0 + t) * 128 + slot] = s;
        g_pQ[(m0 + t) * 128 + slot] = q;
    }
}

// ---------------------------------------------------------------------------
// Pass 3: BN finalize — reduce 128 deterministic partials per channel.
// ---------------------------------------------------------------------------
__global__ void bn_finalize_kernel()
{
    int j = blockIdx.x;
    int t = threadIdx.x;                   // 128 threads
    float s = g_pS[j * 128 + t];
    float q = g_pQ[j * 128 + t];
    #pragma unroll
    for (int o = 16; o > 0; o >>= 1) {
        s += __shfl_down_sync(0xffffffffu, s, o);
        q += __shfl_down_sync(0xffffffffu, q, o);
    }
    __shared__ float ss[4], sq[4];
    int w = t >> 5;
    if ((t & 31) == 0) { ss[w] = s; sq[w] = q; }
    __syncthreads();
    if (t == 0) {
        float S = ss[0] + ss[1] + ss[2] + ss[3];
        float Q = sq[0] + sq[1] + sq[2] + sq[3];
        const float inv = 1.f / (float)(B_ * LS);
        float mean = S * inv;
        float var  = Q * inv - mean * mean;
        g_mean[j] = mean;
        g_rstd[j] = rsqrtf(var + 1e-5f);
    }
}

// ---------------------------------------------------------------------------
// Pass 4: BN + exact GELU + Haar synthesis -> FIRST half of the output
// ---------------------------------------------------------------------------
__device__ __forceinline__ float gelu_exact(float z)
{
    return 0.5f * z * (1.0f + erff(z * 0.70710678118654752440f));
}

__global__ void synth_kernel(const float* __restrict__ S,
                             const float* __restrict__ gamma,
                             const float* __restrict__ beta,
                             float* __restrict__ out)
{
    int tid = blockIdx.x * blockDim.x + threadIdx.x;
    int m = tid & 2047;
    int c = (tid >> 11) & 127;
    int b = (tid >> 18) & 7;
    int p = tid >> 21;

    int j = p * C_ + c;
    float2 y = *(const float2*)(g_y + ((b * PC + j) * LS + (m << 1)));

    float mean = g_mean[j], rstd = g_rstd[j];
    float g = gamma[j], be = beta[j];
    float s00 = S[0], s01 = S[1], s10 = S[2], s11 = S[3];

    float z0 = (y.x - mean) * rstd * g + be;
    float z1 = (y.y - mean) * rstd * g + be;
    float a0 = gelu_exact(z0);
    float a1 = gelu_exact(z1);

    *(float2*)(out + ((long)((p * B_ + b) * C_ + c) << 13) + (m << 1))
        = make_float2(s00 * a0 + s01 * a1, s10 * a0 + s11 * a1);
}

// ---------------------------------------------------------------------------
extern "C" void kernel_launch(void* const* d_in, const int* in_sizes, int n_in,
                              void* d_out, int out_size)
{
    const float* xs    = (const float*)d_in[0];
    const float* A     = (const float*)d_in[1];
    const float* S     = (const float*)d_in[2];
    const float* W     = (const float*)d_in[3];
    const float* gamma = (const float*)d_in[4];
    const float* beta  = (const float*)d_in[5];
    float* out = (float*)d_out;

    static int smem_set = 0;
    if (!smem_set) {
        cudaFuncSetAttribute(gemm_kernel,
                             cudaFuncAttributeMaxDynamicSharedMemorySize, GEMM_SMEM);
        smem_set = 1;
    }

    analysis_kernel<<<dim3(64, 32, 8), 256>>>(xs, A, S, out);
    wsplit_kernel<<<PC * PC / 256, 256>>>(W);
    gemm_kernel<<<dim3(8, 16, 8), 256, GEMM_SMEM>>>();
    bn_finalize_kernel<<<PC, 128>>>();
    synth_kernel<<<P_ * B_ * C_ * (L_ / 4) / 256, 256>>>(S, gamma, beta, out);
}

// round 5
// speedup vs baseline: 3.7592x; 1.3407x over previous
#include <cuda_runtime.h>
#include <cuda_fp16.h>
#include <cstdint>

#define P_  8
#define B_  8
#define C_  128
#define L_  8192
#define PC  1024          // P*C
#define LS  4096          // L/2

// ---------------------------------------------------------------------------
// Static device scratch (no runtime allocation allowed)
// ---------------------------------------------------------------------------
__device__ __align__(16) __half g_D16[PC * PC];                   //  2 MB  W - I (fp16)
__device__ __align__(16) __half g_Xt [(long)B_ * LS * PC];        // 64 MB  sc^T [b][l][j] fp16
__device__ __align__(16) float  g_sc [(long)B_ * PC * LS];        //128 MB  sc   [b][j][l]
__device__ __align__(16) float  g_y  [(long)B_ * PC * LS];        //128 MB  y    [b][j][l]
__device__ float g_pS[PC * 128];   // per-channel partial sums   [j][slot]
__device__ float g_pQ[PC * 128];   // per-channel partial sumsq  [j][slot]
__device__ float g_mean[PC];
__device__ float g_rstd[PC];

__device__ __forceinline__ uint32_t smem_u32(const void* p) {
    uint32_t a;
    asm("{ .reg .u64 t; cvta.to.shared.u64 t, %1; cvt.u32.u64 %0, t; }" : "=r"(a) : "l"(p));
    return a;
}

#define CP_ASYNC16(saddr, gptr) \
    asm volatile("cp.async.cg.shared.global [%0], [%1], 16;" :: "r"(saddr), "l"(gptr))
#define CP_COMMIT() asm volatile("cp.async.commit_group;")
#define CP_WAIT1()  asm volatile("cp.async.wait_group 1;")

#define LDSM4(r0, r1, r2, r3, addr) \
    asm volatile("ldmatrix.sync.aligned.m8n8.x4.shared.b16 {%0,%1,%2,%3}, [%4];" \
        : "=r"(r0), "=r"(r1), "=r"(r2), "=r"(r3) : "r"(addr))

#define MMA16816(acc, a, b) \
    asm volatile("mma.sync.aligned.m16n8k16.row.col.f32.f16.f16.f32 " \
        "{%0,%1,%2,%3}, {%4,%5,%6,%7}, {%8,%9}, {%0,%1,%2,%3};" \
        : "+f"((acc)[0]), "+f"((acc)[1]), "+f"((acc)[2]), "+f"((acc)[3]) \
        : "r"((a)[0]), "r"((a)[1]), "r"((a)[2]), "r"((a)[3]), \
          "r"((b)[0]), "r"((b)[1]))

// ---------------------------------------------------------------------------
// Pass 1: Haar analysis. Writes detail-half of output directly, exact fp32
// sc into g_sc [b][j][l], and fp16 sc TRANSPOSED into g_Xt [b][l][j].
// ---------------------------------------------------------------------------
__global__ __launch_bounds__(256) void analysis_kernel(
    const float* __restrict__ xs, const float* __restrict__ A,
    const float* __restrict__ S, float* __restrict__ out)
{
    __shared__ __half sh[64][33];
    const int t = threadIdx.x;
    const int b = blockIdx.z;
    const int J0 = blockIdx.y * 32;
    const int M0 = blockIdx.x * 32;

    const float a00 = A[0], a01 = A[1], a10 = A[2], a11 = A[3];
    const float s00 = S[0], s01 = S[1], s10 = S[2], s11 = S[3];

    const int m  = t & 31;
    const int jr = t >> 5;
    #pragma unroll
    for (int jl = 0; jl < 4; jl++) {
        int jj = jr + 8 * jl;
        int j = J0 + jj;
        int p = j >> 7, c = j & 127;
        long base = ((long)((p * B_ + b) * C_ + c)) << 13;   // *8192
        float4 x4 = *(const float4*)(xs + base + 4 * (M0 + m));
        float sc0 = a00 * x4.x + a01 * x4.y;
        float sc1 = a00 * x4.z + a01 * x4.w;
        float d0  = a10 * x4.x + a11 * x4.y;
        float d1  = a10 * x4.z + a11 * x4.w;
        *(float2*)(out + base + LS + 2 * (M0 + m))
            = make_float2(s00 * d0 + s01 * d1, s10 * d0 + s11 * d1);
        *(float2*)(g_sc + ((long)(b * PC + j)) * LS + 2 * (M0 + m))
            = make_float2(sc0, sc1);
        sh[2 * m][jj]     = __float2half(sc0);
        sh[2 * m + 1][jj] = __float2half(sc1);
    }
    __syncthreads();
    const int jj = t & 31;
    const int nr = t >> 5;
    #pragma unroll
    for (int i = 0; i < 8; i++) {
        int n = nr + 8 * i;
        g_Xt[((long)(b * LS + 2 * M0 + n)) * PC + J0 + jj] = sh[n][jj];
    }
}

// ---------------------------------------------------------------------------
// D = W - I in fp16
// ---------------------------------------------------------------------------
__global__ void wsplit_kernel(const float* __restrict__ W)
{
    int i = blockIdx.x * 256 + threadIdx.x;
    int row = i >> 10, col = i & 1023;
    float d = W[i] - (row == col ? 1.0f : 0.0f);
    g_D16[i] = __float2half(d);
}

// ---------------------------------------------------------------------------
// Pass 2: HMMA fp16 GEMM  y = sc + D@sc (single term, K=1024).
// CTA 128(M) x 256(N), 256 threads (2x4 warps of 64x64), 32 K-iterations of
// BK=32, 3-stage cp.async pipeline {A|B}, one __syncthreads per iter.
// Epilogue: y = sc + acc, plus deterministic per-row BN partial sums.
// ---------------------------------------------------------------------------
#define STAGE_B 24576          // A 8KB | B 16KB
#define GEMM_SMEM (3 * STAGE_B)

__device__ __forceinline__ void load_stage(uint32_t sbase, int stg,
    const __half* __restrict__ Asrc,
    const __half* __restrict__ Bsrc, int kk, int t)
{
    uint32_t sa = sbase + stg * STAGE_B;
    {                                                 // A: 128 rows x 4 chunks
        int idx = t * 2;                              // 2 consecutive chunks/thread
        int row = idx >> 2, c = idx & 3;
        uint32_t sw0 = (uint32_t)(((c)     ^ ((row >> 1) & 3)) << 4);
        uint32_t sw1 = (uint32_t)(((c + 1) ^ ((row >> 1) & 3)) << 4);
        const __half* g = Asrc + (long)row * PC + kk * 32 + c * 8;
        CP_ASYNC16(sa + row * 64 + sw0, g);
        CP_ASYNC16(sa + row * 64 + sw1, g + 8);
    }
    #pragma unroll
    for (int i = 0; i < 4; i++) {                     // B: 256 rows x 4 chunks
        int idx = t + 256 * i;
        int row = idx >> 2, c = idx & 3;
        uint32_t sw = (uint32_t)((c ^ ((row >> 1) & 3)) << 4);
        const __half* g = Bsrc + (long)row * PC + kk * 32 + c * 8;
        CP_ASYNC16(sa + 8192 + row * 64 + sw, g);
    }
}

__global__ void __launch_bounds__(256, 1) gemm_kernel()
{
    extern __shared__ char smem[];
    const uint32_t sbase = smem_u32(smem);
    const int t    = threadIdx.x;
    const int lane = t & 31;
    const int wid  = t >> 5;
    const int wm   = wid >> 2;            // 0..1
    const int wn   = wid & 3;             // 0..3
    const int m0   = blockIdx.x * 128;
    const int n0   = blockIdx.y * 256;
    const int b    = blockIdx.z;

    const __half* Asrc = g_D16 + (long)m0 * PC;
    const __half* Bsrc = g_Xt + ((long)b * LS + n0) * PC;

    // per-lane ldmatrix constants
    const int rA  = lane & 15;
    const int hkA = lane >> 4;
    const int cA  = (rA >> 1) & 3;
    const uint32_t offA = (uint32_t)(wm * 64 + rA) * 64;
    const int rB  = (lane & 7) | ((lane >> 4) << 3);
    const int hkB = (lane >> 3) & 1;
    const int cB  = (rB >> 1) & 3;
    const uint32_t offB = 8192u + (uint32_t)(wn * 64 + rB) * 64;

    float acc[4][8][4];
    #pragma unroll
    for (int mi = 0; mi < 4; mi++)
        #pragma unroll
        for (int ni = 0; ni < 8; ni++)
            #pragma unroll
            for (int q = 0; q < 4; q++) acc[mi][ni][q] = 0.f;

    load_stage(sbase, 0, Asrc, Bsrc, 0, t); CP_COMMIT();
    load_stage(sbase, 1, Asrc, Bsrc, 1, t); CP_COMMIT();

    int stg = 0;
    for (int kt = 0; kt < 32; kt++) {
        CP_WAIT1();
        __syncthreads();
        {
            int kn = kt + 2;
            if (kn < 32) {
                int stn = stg + 2; if (stn >= 3) stn -= 3;
                load_stage(sbase, stn, Asrc, Bsrc, kn, t);
            }
            CP_COMMIT();
        }
        uint32_t sa = sbase + stg * STAGE_B;
        #pragma unroll
        for (int s2 = 0; s2 < 2; s2++) {
            uint32_t bf[8][2];
            #pragma unroll
            for (int p = 0; p < 4; p++) {
                uint32_t addr = sa + offB + p * (16 * 64)
                              + (uint32_t)(((2 * s2 + hkB) ^ cB) << 4);
                LDSM4(bf[2 * p][0], bf[2 * p][1], bf[2 * p + 1][0], bf[2 * p + 1][1], addr);
            }
            uint32_t a[4][4];
            #pragma unroll
            for (int mi = 0; mi < 4; mi++) {
                uint32_t addr = sa + offA + mi * (16 * 64)
                              + (uint32_t)(((2 * s2 + hkA) ^ cA) << 4);
                LDSM4(a[mi][0], a[mi][1], a[mi][2], a[mi][3], addr);
            }
            #pragma unroll
            for (int mi = 0; mi < 4; mi++)
                #pragma unroll
                for (int ni = 0; ni < 8; ni++)
                    MMA16816(acc[mi][ni], a[mi], bf[ni]);
        }
        if (++stg == 3) stg = 0;
    }

    // ------------------- Epilogue: y = sc + acc, BN partials ---------------
    __syncthreads();                       // smem stages -> scratch
    float* sS = (float*)smem;              // [128][4]
    float* sQ = (float*)smem + 512;        // [128][4]

    const int rl = wm * 64 + (lane >> 2);  // local row base
    const int c0 = n0 + wn * 64 + (lane & 3) * 2;
    #pragma unroll
    for (int mi = 0; mi < 4; mi++) {
        int rla = rl + mi * 16, rlb = rla + 8;
        long oa = ((long)b * PC + m0 + rla) * LS + c0;
        long ob = ((long)b * PC + m0 + rlb) * LS + c0;
        float sa_ = 0.f, qa_ = 0.f, sb_ = 0.f, qb_ = 0.f;
        #pragma unroll
        for (int ni = 0; ni < 8; ni++) {
            float2 v0 = *(const float2*)(g_sc + oa + ni * 8);
            float2 v1 = *(const float2*)(g_sc + ob + ni * 8);
            float y0 = acc[mi][ni][0] + v0.x, y1 = acc[mi][ni][1] + v0.y;
            float y2 = acc[mi][ni][2] + v1.x, y3 = acc[mi][ni][3] + v1.y;
            *(float2*)(g_y + oa + ni * 8) = make_float2(y0, y1);
            *(float2*)(g_y + ob + ni * 8) = make_float2(y2, y3);
            sa_ += y0 + y1; qa_ += y0 * y0 + y1 * y1;
            sb_ += y2 + y3; qb_ += y2 * y2 + y3 * y3;
        }
        sa_ += __shfl_xor_sync(0xffffffffu, sa_, 1);
        sa_ += __shfl_xor_sync(0xffffffffu, sa_, 2);
        qa_ += __shfl_xor_sync(0xffffffffu, qa_, 1);
        qa_ += __shfl_xor_sync(0xffffffffu, qa_, 2);
        sb_ += __shfl_xor_sync(0xffffffffu, sb_, 1);
        sb_ += __shfl_xor_sync(0xffffffffu, sb_, 2);
        qb_ += __shfl_xor_sync(0xffffffffu, qb_, 1);
        qb_ += __shfl_xor_sync(0xffffffffu, qb_, 2);
        if ((lane & 3) == 0) {
            sS[rla * 4 + wn] = sa_; sQ[rla * 4 + wn] = qa_;
            sS[rlb * 4 + wn] = sb_; sQ[rlb * 4 + wn] = qb_;
        }
    }
    __syncthreads();
    if (t < 128) {
        float s = sS[t * 4] + sS[t * 4 + 1] + sS[t * 4 + 2] + sS[t * 4 + 3];
        float q = sQ[t * 4] + sQ[t * 4 + 1] + sQ[t * 4 + 2] + sQ[t * 4 + 3];
        int slot = b * 16 + blockIdx.y;    // 128 slots per channel
        g_pS[(m0 + t) * 128 + slot] = s;
        g_pQ[(m0 + t) * 128 + slot] = q;
    }
}

// ---------------------------------------------------------------------------
// Pass 3: BN finalize — reduce 128 deterministic partials per channel.
// ---------------------------------------------------------------------------
__global__ void bn_finalize_kernel()
{
    int j = blockIdx.x;
    int t = threadIdx.x;                   // 128 threads
    float s = g_pS[j * 128 + t];
    float q = g_pQ[j * 128 + t];
    #pragma unroll
    for (int o = 16; o > 0; o >>= 1) {
        s += __shfl_down_sync(0xffffffffu, s, o);
        q += __shfl_down_sync(0xffffffffu, q, o);
    }
    __shared__ float ss[4], sq[4];
    int w = t >> 5;
    if ((t & 31) == 0) { ss[w] = s; sq[w] = q; }
    __syncthreads();
    if (t == 0) {
        float S = ss[0] + ss[1] + ss[2] + ss[3];
        float Q = sq[0] + sq[1] + sq[2] + sq[3];
        const float inv = 1.f / (float)(B_ * LS);
        float mean = S * inv;
        float var  = Q * inv - mean * mean;
        g_mean[j] = mean;
        g_rstd[j] = rsqrtf(var + 1e-5f);
    }
}

// ---------------------------------------------------------------------------
// Pass 4: BN + exact GELU + Haar synthesis -> FIRST half of the output.
// 8 values per thread (2x float4 in / 2x float4 out).
// ---------------------------------------------------------------------------
__device__ __forceinline__ float gelu_exact(float z)
{
    return 0.5f * z * (1.0f + erff(z * 0.70710678118654752440f));
}

__global__ __launch_bounds__(256) void synth_kernel(
    const float* __restrict__ S,
    const float* __restrict__ gamma,
    const float* __restrict__ beta,
    float* __restrict__ out)
{
    int tid = blockIdx.x * blockDim.x + threadIdx.x;   // < P*B*C*512
    int m8 = tid & 511;                  // group of 8 l-values
    int c  = (tid >> 9) & 127;
    int b  = (tid >> 16) & 7;
    int p  = tid >> 19;

    int j = p * C_ + c;
    const float* yp = g_y + ((long)(b * PC + j)) * LS + 8 * m8;
    float4 ya = *(const float4*)yp;
    float4 yb = *(const float4*)(yp + 4);

    float mean = g_mean[j], rstd = g_rstd[j];
    float gm = gamma[j] * rstd;
    float bo = beta[j] - mean * gm;
    float s00 = S[0], s01 = S[1], s10 = S[2], s11 = S[3];

    float a0 = gelu_exact(ya.x * gm + bo);
    float a1 = gelu_exact(ya.y * gm + bo);
    float a2 = gelu_exact(ya.z * gm + bo);
    float a3 = gelu_exact(ya.w * gm + bo);
    float a4 = gelu_exact(yb.x * gm + bo);
    float a5 = gelu_exact(yb.y * gm + bo);
    float a6 = gelu_exact(yb.z * gm + bo);
    float a7 = gelu_exact(yb.w * gm + bo);

    float4 o0 = make_float4(s00 * a0 + s01 * a1, s10 * a0 + s11 * a1,
                            s00 * a2 + s01 * a3, s10 * a2 + s11 * a3);
    float4 o1 = make_float4(s00 * a4 + s01 * a5, s10 * a4 + s11 * a5,
                            s00 * a6 + s01 * a7, s10 * a6 + s11 * a7);

    float* op = out + (((long)((p * B_ + b) * C_ + c)) << 13) + 8 * m8;
    *(float4*)op       = o0;
    *(float4*)(op + 4) = o1;
}

// ---------------------------------------------------------------------------
extern "C" void kernel_launch(void* const* d_in, const int* in_sizes, int n_in,
                              void* d_out, int out_size)
{
    const float* xs    = (const float*)d_in[0];
    const float* A     = (const float*)d_in[1];
    const float* S     = (const float*)d_in[2];
    const float* W     = (const float*)d_in[3];
    const float* gamma = (const float*)d_in[4];
    const float* beta  = (const float*)d_in[5];
    float* out = (float*)d_out;

    static int smem_set = 0;
    if (!smem_set) {
        cudaFuncSetAttribute(gemm_kernel,
                             cudaFuncAttributeMaxDynamicSharedMemorySize, GEMM_SMEM);
        smem_set = 1;
    }

    analysis_kernel<<<dim3(64, 32, 8), 256>>>(xs, A, S, out);
    wsplit_kernel<<<PC * PC / 256, 256>>>(W);
    gemm_kernel<<<dim3(8, 16, 8), 256, GEMM_SMEM>>>();
    bn_finalize_kernel<<<PC, 128>>>();
    synth_kernel<<<P_ * B_ * C_ * (LS / 8) / 256, 256>>>(S, gamma, beta, out);
}

// round 6
// speedup vs baseline: 4.6871x; 1.2468x over previous
#include <cuda_runtime.h>
#include <cuda_fp16.h>
#include <cstdint>

#define P_  8
#define B_  8
#define C_  128
#define L_  8192
#define PC  1024          // P*C
#define LS  4096          // L/2

// ---------------------------------------------------------------------------
// Static device scratch (no runtime allocation allowed)
// ---------------------------------------------------------------------------
__device__ __align__(16) __half g_W16[PC * PC];                   //  2 MB  W (fp16)
__device__ __align__(16) __half g_Xt [(long)B_ * LS * PC];        // 64 MB  sc^T [b][l][j] fp16
__device__ __align__(16) __half g_y16[(long)B_ * PC * LS];        // 64 MB  y    [b][j][l] fp16
__device__ float g_pS[PC * 128];   // per-channel partial sums   [j][slot]
__device__ float g_pQ[PC * 128];   // per-channel partial sumsq  [j][slot]
__device__ float g_mean[PC];
__device__ float g_rstd[PC];

__device__ __forceinline__ uint32_t smem_u32(const void* p) {
    uint32_t a;
    asm("{ .reg .u64 t; cvta.to.shared.u64 t, %1; cvt.u32.u64 %0, t; }" : "=r"(a) : "l"(p));
    return a;
}

#define CP_ASYNC16(saddr, gptr) \
    asm volatile("cp.async.cg.shared.global [%0], [%1], 16;" :: "r"(saddr), "l"(gptr))
#define CP_COMMIT() asm volatile("cp.async.commit_group;")
#define CP_WAIT1()  asm volatile("cp.async.wait_group 1;")

#define LDSM4(r0, r1, r2, r3, addr) \
    asm volatile("ldmatrix.sync.aligned.m8n8.x4.shared.b16 {%0,%1,%2,%3}, [%4];" \
        : "=r"(r0), "=r"(r1), "=r"(r2), "=r"(r3) : "r"(addr))

#define MMA16816(acc, a, b) \
    asm volatile("mma.sync.aligned.m16n8k16.row.col.f32.f16.f16.f32 " \
        "{%0,%1,%2,%3}, {%4,%5,%6,%7}, {%8,%9}, {%0,%1,%2,%3};" \
        : "+f"((acc)[0]), "+f"((acc)[1]), "+f"((acc)[2]), "+f"((acc)[3]) \
        : "r"((a)[0]), "r"((a)[1]), "r"((a)[2]), "r"((a)[3]), \
          "r"((b)[0]), "r"((b)[1]))

// ---------------------------------------------------------------------------
// Pass 1: Haar analysis. Writes detail-half of output directly and fp16 sc
// TRANSPOSED into g_Xt [b][l][j]. (No fp32 sc copy anymore.)
// ---------------------------------------------------------------------------
__global__ __launch_bounds__(256) void analysis_kernel(
    const float* __restrict__ xs, const float* __restrict__ A,
    const float* __restrict__ S, float* __restrict__ out)
{
    __shared__ __half sh[64][33];
    const int t = threadIdx.x;
    const int b = blockIdx.z;
    const int J0 = blockIdx.y * 32;
    const int M0 = blockIdx.x * 32;

    const float a00 = A[0], a01 = A[1], a10 = A[2], a11 = A[3];
    const float s00 = S[0], s01 = S[1], s10 = S[2], s11 = S[3];

    const int m  = t & 31;
    const int jr = t >> 5;
    #pragma unroll
    for (int jl = 0; jl < 4; jl++) {
        int jj = jr + 8 * jl;
        int j = J0 + jj;
        int p = j >> 7, c = j & 127;
        long base = ((long)((p * B_ + b) * C_ + c)) << 13;   // *8192
        float4 x4 = *(const float4*)(xs + base + 4 * (M0 + m));
        float sc0 = a00 * x4.x + a01 * x4.y;
        float sc1 = a00 * x4.z + a01 * x4.w;
        float d0  = a10 * x4.x + a11 * x4.y;
        float d1  = a10 * x4.z + a11 * x4.w;
        *(float2*)(out + base + LS + 2 * (M0 + m))
            = make_float2(s00 * d0 + s01 * d1, s10 * d0 + s11 * d1);
        sh[2 * m][jj]     = __float2half(sc0);
        sh[2 * m + 1][jj] = __float2half(sc1);
    }
    __syncthreads();
    const int jj = t & 31;
    const int nr = t >> 5;
    #pragma unroll
    for (int i = 0; i < 8; i++) {
        int n = nr + 8 * i;
        g_Xt[((long)(b * LS + 2 * M0 + n)) * PC + J0 + jj] = sh[n][jj];
    }
}

// ---------------------------------------------------------------------------
// W in fp16 (full matrix — identity included; error attenuated by fp32 accum)
// ---------------------------------------------------------------------------
__global__ void wsplit_kernel(const float* __restrict__ W)
{
    int i = blockIdx.x * 256 + threadIdx.x;
    g_W16[i] = __float2half(W[i]);
}

// ---------------------------------------------------------------------------
// Pass 2: HMMA fp16 GEMM  y = W@sc (K=1024), fp32 accumulate.
// CTA 128(M) x 256(N), 256 threads (2x4 warps of 64x64), 32 K-iterations of
// BK=32, 3-stage cp.async pipeline {A|B}, one __syncthreads per iter.
// Epilogue: write y as fp16, deterministic per-row BN partials from fp32 regs.
// ---------------------------------------------------------------------------
#define STAGE_B 24576          // A 8KB | B 16KB
#define GEMM_SMEM (3 * STAGE_B)

__device__ __forceinline__ void load_stage(uint32_t sbase, int stg,
    const __half* __restrict__ Asrc,
    const __half* __restrict__ Bsrc, int kk, int t)
{
    uint32_t sa = sbase + stg * STAGE_B;
    {                                                 // A: 128 rows x 4 chunks
        int idx = t * 2;                              // 2 consecutive chunks/thread
        int row = idx >> 2, c = idx & 3;
        uint32_t sw0 = (uint32_t)(((c)     ^ ((row >> 1) & 3)) << 4);
        uint32_t sw1 = (uint32_t)(((c + 1) ^ ((row >> 1) & 3)) << 4);
        const __half* g = Asrc + (long)row * PC + kk * 32 + c * 8;
        CP_ASYNC16(sa + row * 64 + sw0, g);
        CP_ASYNC16(sa + row * 64 + sw1, g + 8);
    }
    #pragma unroll
    for (int i = 0; i < 4; i++) {                     // B: 256 rows x 4 chunks
        int idx = t + 256 * i;
        int row = idx >> 2, c = idx & 3;
        uint32_t sw = (uint32_t)((c ^ ((row >> 1) & 3)) << 4);
        const __half* g = Bsrc + (long)row * PC + kk * 32 + c * 8;
        CP_ASYNC16(sa + 8192 + row * 64 + sw, g);
    }
}

__global__ void __launch_bounds__(256, 1) gemm_kernel()
{
    extern __shared__ char smem[];
    const uint32_t sbase = smem_u32(smem);
    const int t    = threadIdx.x;
    const int lane = t & 31;
    const int wid  = t >> 5;
    const int wm   = wid >> 2;            // 0..1
    const int wn   = wid & 3;             // 0..3
    const int m0   = blockIdx.x * 128;
    const int n0   = blockIdx.y * 256;
    const int b    = blockIdx.z;

    const __half* Asrc = g_W16 + (long)m0 * PC;
    const __half* Bsrc = g_Xt + ((long)b * LS + n0) * PC;

    // per-lane ldmatrix constants
    const int rA  = lane & 15;
    const int hkA = lane >> 4;
    const int cA  = (rA >> 1) & 3;
    const uint32_t offA = (uint32_t)(wm * 64 + rA) * 64;
    const int rB  = (lane & 7) | ((lane >> 4) << 3);
    const int hkB = (lane >> 3) & 1;
    const int cB  = (rB >> 1) & 3;
    const uint32_t offB = 8192u + (uint32_t)(wn * 64 + rB) * 64;

    float acc[4][8][4];
    #pragma unroll
    for (int mi = 0; mi < 4; mi++)
        #pragma unroll
        for (int ni = 0; ni < 8; ni++)
            #pragma unroll
            for (int q = 0; q < 4; q++) acc[mi][ni][q] = 0.f;

    load_stage(sbase, 0, Asrc, Bsrc, 0, t); CP_COMMIT();
    load_stage(sbase, 1, Asrc, Bsrc, 1, t); CP_COMMIT();

    int stg = 0;
    for (int kt = 0; kt < 32; kt++) {
        CP_WAIT1();
        __syncthreads();
        {
            int kn = kt + 2;
            if (kn < 32) {
                int stn = stg + 2; if (stn >= 3) stn -= 3;
                load_stage(sbase, stn, Asrc, Bsrc, kn, t);
            }
            CP_COMMIT();
        }
        uint32_t sa = sbase + stg * STAGE_B;
        #pragma unroll
        for (int s2 = 0; s2 < 2; s2++) {
            uint32_t bf[8][2];
            #pragma unroll
            for (int p = 0; p < 4; p++) {
                uint32_t addr = sa + offB + p * (16 * 64)
                              + (uint32_t)(((2 * s2 + hkB) ^ cB) << 4);
                LDSM4(bf[2 * p][0], bf[2 * p][1], bf[2 * p + 1][0], bf[2 * p + 1][1], addr);
            }
            uint32_t a[4][4];
            #pragma unroll
            for (int mi = 0; mi < 4; mi++) {
                uint32_t addr = sa + offA + mi * (16 * 64)
                              + (uint32_t)(((2 * s2 + hkA) ^ cA) << 4);
                LDSM4(a[mi][0], a[mi][1], a[mi][2], a[mi][3], addr);
            }
            #pragma unroll
            for (int mi = 0; mi < 4; mi++)
                #pragma unroll
                for (int ni = 0; ni < 8; ni++)
                    MMA16816(acc[mi][ni], a[mi], bf[ni]);
        }
        if (++stg == 3) stg = 0;
    }

    // ------------- Epilogue: y(fp16) = acc, BN partials from fp32 ----------
    __syncthreads();                       // smem stages -> scratch
    float* sS = (float*)smem;              // [128][4]
    float* sQ = (float*)smem + 512;        // [128][4]

    const int rl = wm * 64 + (lane >> 2);  // local row base
    const int c0 = n0 + wn * 64 + (lane & 3) * 2;
    #pragma unroll
    for (int mi = 0; mi < 4; mi++) {
        int rla = rl + mi * 16, rlb = rla + 8;
        long oa = ((long)b * PC + m0 + rla) * LS + c0;
        long ob = ((long)b * PC + m0 + rlb) * LS + c0;
        float sa_ = 0.f, qa_ = 0.f, sb_ = 0.f, qb_ = 0.f;
        #pragma unroll
        for (int ni = 0; ni < 8; ni++) {
            float y0 = acc[mi][ni][0], y1 = acc[mi][ni][1];
            float y2 = acc[mi][ni][2], y3 = acc[mi][ni][3];
            *(__half2*)(g_y16 + oa + ni * 8) = __floats2half2_rn(y0, y1);
            *(__half2*)(g_y16 + ob + ni * 8) = __floats2half2_rn(y2, y3);
            sa_ += y0 + y1; qa_ += y0 * y0 + y1 * y1;
            sb_ += y2 + y3; qb_ += y2 * y2 + y3 * y3;
        }
        sa_ += __shfl_xor_sync(0xffffffffu, sa_, 1);
        sa_ += __shfl_xor_sync(0xffffffffu, sa_, 2);
        qa_ += __shfl_xor_sync(0xffffffffu, qa_, 1);
        qa_ += __shfl_xor_sync(0xffffffffu, qa_, 2);
        sb_ += __shfl_xor_sync(0xffffffffu, sb_, 1);
        sb_ += __shfl_xor_sync(0xffffffffu, sb_, 2);
        qb_ += __shfl_xor_sync(0xffffffffu, qb_, 1);
        qb_ += __shfl_xor_sync(0xffffffffu, qb_, 2);
        if ((lane & 3) == 0) {
            sS[rla * 4 + wn] = sa_; sQ[rla * 4 + wn] = qa_;
            sS[rlb * 4 + wn] = sb_; sQ[rlb * 4 + wn] = qb_;
        }
    }
    __syncthreads();
    if (t < 128) {
        float s = sS[t * 4] + sS[t * 4 + 1] + sS[t * 4 + 2] + sS[t * 4 + 3];
        float q = sQ[t * 4] + sQ[t * 4 + 1] + sQ[t * 4 + 2] + sQ[t * 4 + 3];
        int slot = b * 16 + blockIdx.y;    // 128 slots per channel
        g_pS[(m0 + t) * 128 + slot] = s;
        g_pQ[(m0 + t) * 128 + slot] = q;
    }
}

// ---------------------------------------------------------------------------
// Pass 3: BN finalize — reduce 128 deterministic partials per channel.
// ---------------------------------------------------------------------------
__global__ void bn_finalize_kernel()
{
    int j = blockIdx.x;
    int t = threadIdx.x;                   // 128 threads
    float s = g_pS[j * 128 + t];
    float q = g_pQ[j * 128 + t];
    #pragma unroll
    for (int o = 16; o > 0; o >>= 1) {
        s += __shfl_down_sync(0xffffffffu, s, o);
        q += __shfl_down_sync(0xffffffffu, q, o);
    }
    __shared__ float ss[4], sq[4];
    int w = t >> 5;
    if ((t & 31) == 0) { ss[w] = s; sq[w] = q; }
    __syncthreads();
    if (t == 0) {
        float S = ss[0] + ss[1] + ss[2] + ss[3];
        float Q = sq[0] + sq[1] + sq[2] + sq[3];
        const float inv = 1.f / (float)(B_ * LS);
        float mean = S * inv;
        float var  = Q * inv - mean * mean;
        g_mean[j] = mean;
        g_rstd[j] = rsqrtf(var + 1e-5f);
    }
}

// ---------------------------------------------------------------------------
// Pass 4: BN + exact GELU + Haar synthesis -> FIRST half of the output.
// 8 fp16 y-values per thread (one uint4 in, 2x float4 out).
// ---------------------------------------------------------------------------
__device__ __forceinline__ float gelu_exact(float z)
{
    return 0.5f * z * (1.0f + erff(z * 0.70710678118654752440f));
}

__global__ __launch_bounds__(256) void synth_kernel(
    const float* __restrict__ S,
    const float* __restrict__ gamma,
    const float* __restrict__ beta,
    float* __restrict__ out)
{
    int tid = blockIdx.x * blockDim.x + threadIdx.x;   // < P*B*C*512
    int m8 = tid & 511;                  // group of 8 l-values
    int c  = (tid >> 9) & 127;
    int b  = (tid >> 16) & 7;
    int p  = tid >> 19;

    int j = p * C_ + c;
    const __half2* yp = (const __half2*)(g_y16 + ((long)(b * PC + j)) * LS + 8 * m8);
    uint4 raw = *(const uint4*)yp;
    float2 v0 = __half22float2(*(const __half2*)&raw.x);
    float2 v1 = __half22float2(*(const __half2*)&raw.y);
    float2 v2 = __half22float2(*(const __half2*)&raw.z);
    float2 v3 = __half22float2(*(const __half2*)&raw.w);

    float mean = g_mean[j], rstd = g_rstd[j];
    float gm = gamma[j] * rstd;
    float bo = beta[j] - mean * gm;
    float s00 = S[0], s01 = S[1], s10 = S[2], s11 = S[3];

    float a0 = gelu_exact(v0.x * gm + bo);
    float a1 = gelu_exact(v0.y * gm + bo);
    float a2 = gelu_exact(v1.x * gm + bo);
    float a3 = gelu_exact(v1.y * gm + bo);
    float a4 = gelu_exact(v2.x * gm + bo);
    float a5 = gelu_exact(v2.y * gm + bo);
    float a6 = gelu_exact(v3.x * gm + bo);
    float a7 = gelu_exact(v3.y * gm + bo);

    float4 o0 = make_float4(s00 * a0 + s01 * a1, s10 * a0 + s11 * a1,
                            s00 * a2 + s01 * a3, s10 * a2 + s11 * a3);
    float4 o1 = make_float4(s00 * a4 + s01 * a5, s10 * a4 + s11 * a5,
                            s00 * a6 + s01 * a7, s10 * a6 + s11 * a7);

    float* op = out + (((long)((p * B_ + b) * C_ + c)) << 13) + 8 * m8;
    *(float4*)op       = o0;
    *(float4*)(op + 4) = o1;
}

// ---------------------------------------------------------------------------
extern "C" void kernel_launch(void* const* d_in, const int* in_sizes, int n_in,
                              void* d_out, int out_size)
{
    const float* xs    = (const float*)d_in[0];
    const float* A     = (const float*)d_in[1];
    const float* S     = (const float*)d_in[2];
    const float* W     = (const float*)d_in[3];
    const float* gamma = (const float*)d_in[4];
    const float* beta  = (const float*)d_in[5];
    float* out = (float*)d_out;

    static int smem_set = 0;
    if (!smem_set) {
        cudaFuncSetAttribute(gemm_kernel,
                             cudaFuncAttributeMaxDynamicSharedMemorySize, GEMM_SMEM);
        smem_set = 1;
    }

    analysis_kernel<<<dim3(64, 32, 8), 256>>>(xs, A, S, out);
    wsplit_kernel<<<PC * PC / 256, 256>>>(W);
    gemm_kernel<<<dim3(8, 16, 8), 256, GEMM_SMEM>>>();
    bn_finalize_kernel<<<PC, 128>>>();
    synth_kernel<<<P_ * B_ * C_ * (LS / 8) / 256, 256>>>(S, gamma, beta, out);
}